// round 16
// baseline (speedup 1.0000x reference)
#include <cuda_runtime.h>
#include <cuda_fp16.h>
#include <mma.h>
#include <cstdint>

using namespace nvcuda;

#define NN 100000
#define EP 1000000
#define EN 500000
#define NBLK ((NN + 1023) / 1024)   // 98
#define FINB (2 * NBLK)             // 196 finalize blocks in fill2
#define NTILES (NN / 16)            // 6250
#define GEMMG ((NTILES + 3) / 4)    // 1563
#define PB ((NN * 16 + 255) / 256)  // 6250 prep blocks
#define WB 16                       // wprep blocks
#define EB ((EP + EN + 255) / 256)  // 5860 edge blocks

// ---------------- scratch (device globals: no allocations allowed) ----------
__device__ __align__(256) __half g_A1[NN * 192];
__device__ __align__(256) __half g_A2[NN * 192];
__device__ __align__(256) __half g_z2[NN * 64];
__device__ __align__(256) __half g_W1[192 * 64];
__device__ __align__(256) __half g_W2[192 * 64];
__device__ __align__(256) __half g_Wo[64 * 64];
__device__ __align__(256) float  g_b1[64];
__device__ __align__(256) float  g_b2[64];
__device__ __align__(256) float  g_b3[64];
// CSR build. INVARIANT: g_pcnt/g_ncnt are zero at kernel_launch entry.
__device__ __align__(256) int  g_pcnt[NN];
__device__ __align__(256) int  g_ncnt[NN];
__device__ __align__(256) int  g_plocal[NN];
__device__ __align__(256) int  g_nlocal[NN];
__device__ __align__(256) int  g_poff[NN + 1];
__device__ __align__(256) int  g_noff[NN + 1];
__device__ __align__(256) int  g_prank[EP];
__device__ __align__(256) int  g_nrank[EN];
__device__ __align__(256) int  g_blksum[2][NBLK];
__device__ __align__(256) int2 g_pedge[EP];
__device__ __align__(256) int2 g_nedge[EN];

// ---------------- helpers ----------------------------------------------------
__device__ __forceinline__ float tanha(float x) {
    float r;
    asm("tanh.approx.f32 %0, %1;" : "=f"(r) : "f"(x));
    return r;
}

// ---------------- launch #0: prep (x->fp16) + weight folding + hist ----------
__global__ void prep_all_kernel(
    const float4* __restrict__ x4,
    const float* __restrict__ w1p, const float* __restrict__ b1p,
    const float* __restrict__ w1n, const float* __restrict__ b1n,
    const float* __restrict__ w2p, const float* __restrict__ b2p,
    const float* __restrict__ w2n, const float* __restrict__ b2n,
    const float* __restrict__ wout, const float* __restrict__ bout,
    const int* __restrict__ pei, const int* __restrict__ nei) {
    int bx = blockIdx.x;
    int tid = threadIdx.x;
    if (bx < PB) {
        int i = bx * 256 + tid;
        if (i < NN * 16) {
            int n = i >> 4, c = i & 15;
            float4 v = x4[i];
            __half2 h0 = __floats2half2_rn(v.x, v.y);
            __half2 h1 = __floats2half2_rn(v.z, v.w);
            uint2 u;
            u.x = *reinterpret_cast<const unsigned*>(&h0);
            u.y = *reinterpret_cast<const unsigned*>(&h1);
            reinterpret_cast<uint2*>(g_A1)[n * 48 + 32 + c] = u;
        }
    } else if (bx < PB + WB) {
        int t = (bx - PB) * 256 + tid;
        int stride = WB * 256;
        for (int i = t; i < 192 * 64; i += stride) {
            int k = i >> 6, j = i & 63;
            float v = 0.f;
            if (j < 32) {
                if (k < 64) v = w1p[k * 32 + j];
                else if (k >= 128) v = w1p[(k - 64) * 32 + j];
            } else {
                int jj = j - 32;
                if (k >= 64) v = w1n[(k - 64) * 32 + jj];
            }
            g_W1[i] = __float2half(v);
            float u = 0.f;
            if (j < 32) {
                if (k < 32) u = w2p[k * 32 + j];
                else if (k >= 64 && k < 96) u = w2p[(k - 32) * 32 + j];
                else if (k >= 128 && k < 160) u = w2p[(k - 64) * 32 + j];
            } else {
                int jj = j - 32;
                if (k >= 32 && k < 64) u = w2n[(k - 32) * 32 + jj];
                else if (k >= 96 && k < 128) u = w2n[(k - 64) * 32 + jj];
                else if (k >= 160) u = w2n[(k - 96) * 32 + jj];
            }
            g_W2[i] = __float2half(u);
        }
        for (int i = t; i < 64 * 64; i += stride) g_Wo[i] = __float2half(wout[i]);
        for (int i = t; i < 64; i += stride) {
            g_b1[i] = (i < 32) ? b1p[i] : b1n[i - 32];
            g_b2[i] = (i < 32) ? b2p[i] : b2n[i - 32];
            g_b3[i] = bout[i];
        }
    } else {
        int t = (bx - PB - WB) * 256 + tid;
        if (t < EP) {
            int d = pei[EP + t];
            g_prank[t] = atomicAdd(&g_pcnt[d], 1);
        } else if (t < EP + EN) {
            int e = t - EP;
            int d = nei[EN + e];
            g_nrank[e] = atomicAdd(&g_ncnt[d], 1);
        }
    }
}

// ---------------- launch #1: per-block exclusive scan ------------------------
__global__ void scan1_kernel() {
    __shared__ int swsum[32];
    int arr = blockIdx.y;
    const int* cnt = arr ? g_ncnt : g_pcnt;
    int* loc = arr ? g_nlocal : g_plocal;
    int tid = threadIdx.x, lane = tid & 31, wid = tid >> 5;
    int i = blockIdx.x * 1024 + tid;
    int v = (i < NN) ? cnt[i] : 0;
    int val = v;
#pragma unroll
    for (int o = 1; o < 32; o <<= 1) {
        int t2 = __shfl_up_sync(0xFFFFFFFFu, val, o);
        if (lane >= o) val += t2;
    }
    if (lane == 31) swsum[wid] = val;
    __syncthreads();
    if (wid == 0) {
        int s = swsum[lane];
#pragma unroll
        for (int o = 1; o < 32; o <<= 1) {
            int t2 = __shfl_up_sync(0xFFFFFFFFu, s, o);
            if (lane >= o) s += t2;
        }
        swsum[lane] = s;
    }
    __syncthreads();
    int woff = wid ? swsum[wid - 1] : 0;
    int incl = val + woff;
    if (i < NN) loc[i] = incl - v;
    if (tid == 1023) g_blksum[arr][blockIdx.x] = incl;
}

// ---------------- launch #2: finalize offsets + fill CSR (+ re-zero cnts) ----
__global__ void fill2_kernel(const int* __restrict__ pei, const int* __restrict__ nei,
                             const float* __restrict__ pw, const float* __restrict__ nw) {
    int bx = blockIdx.x;
    int tid = threadIdx.x;
    if (bx < FINB) {
        int arr = bx / NBLK;
        int b = bx % NBLK;
        __shared__ int s_pref;
        if (tid < 32) {
            int acc = 0;
            for (int idx = tid; idx < b; idx += 32) acc += g_blksum[arr][idx];
#pragma unroll
            for (int o = 16; o; o >>= 1) acc += __shfl_xor_sync(0xFFFFFFFFu, acc, o);
            if (tid == 0) s_pref = acc;
        }
        __syncthreads();
        int pref = s_pref;
        const int* loc = arr ? g_nlocal : g_plocal;
        int* off = arr ? g_noff : g_poff;
        int* cnt = arr ? g_ncnt : g_pcnt;
#pragma unroll
        for (int k = 0; k < 4; k++) {
            int i = b * 1024 + k * 256 + tid;
            if (i < NN) {
                off[i] = loc[i] + pref;
                cnt[i] = 0;
            }
        }
        if (b == NBLK - 1 && tid == 0)
            off[NN] = pref + g_blksum[arr][NBLK - 1];
    } else {
        __shared__ int spref[2][NBLK];
        int wid = tid >> 5, lane = tid & 31;
        if (wid < 2) {
            int carry = 0;
            for (int base = 0; base < NBLK; base += 32) {
                int idx = base + lane;
                int v = (idx < NBLK) ? g_blksum[wid][idx] : 0;
                int s = v;
#pragma unroll
                for (int o = 1; o < 32; o <<= 1) {
                    int t2 = __shfl_up_sync(0xFFFFFFFFu, s, o);
                    if (lane >= o) s += t2;
                }
                if (idx < NBLK) spref[wid][idx] = carry + s - v;
                carry += __shfl_sync(0xFFFFFFFFu, s, 31);
            }
        }
        __syncthreads();
        int t = (bx - FINB) * 256 + tid;
        if (t < EP) {
            int dst = pei[EP + t];
            int slot = g_plocal[dst] + spref[0][dst >> 10] + g_prank[t];
            g_pedge[slot] = make_int2(pei[t], __float_as_int(pw[t]));
        } else if (t < EP + EN) {
            int e = t - EP;
            int dst = nei[EN + e];
            int slot = g_nlocal[dst] + spref[1][dst >> 10] + g_nrank[e];
            g_nedge[slot] = make_int2(nei[e], __float_as_int(nw[e]));
        }
    }
}

// ---------------- CSR gather (launch #3 = ncu capture target) ----------------
__device__ __forceinline__ void h4acc(uint2 r, float w, float4& acc) {
    __half2 ha = *reinterpret_cast<__half2*>(&r.x);
    __half2 hb = *reinterpret_cast<__half2*>(&r.y);
    float2 fa = __half22float2(ha);
    float2 fb = __half22float2(hb);
    acc.x += w * fa.x; acc.y += w * fa.y;
    acc.z += w * fb.x; acc.w += w * fb.y;
}

__global__ void gather_kernel(const __half* __restrict__ featA,
                              __half* __restrict__ dstA, int swap) {
    int t = blockIdx.x * blockDim.x + threadIdx.x;
    int n = t >> 4;
    if (n >= NN) return;
    int c = t & 15;
    const uint2* feat = reinterpret_cast<const uint2*>(featA);

    float4 accA = make_float4(0.f, 0.f, 0.f, 0.f);
    float wsumA = 0.f;
    {
        int b = g_poff[n], e = g_poff[n + 1];
        int i = b;
        for (; i + 4 <= e; i += 4) {
            int2 e0 = g_pedge[i + 0];
            int2 e1 = g_pedge[i + 1];
            int2 e2 = g_pedge[i + 2];
            int2 e3 = g_pedge[i + 3];
            uint2 r0 = __ldg(&feat[e0.x * 48 + 32 + c]);
            uint2 r1 = __ldg(&feat[e1.x * 48 + 32 + c]);
            uint2 r2 = __ldg(&feat[e2.x * 48 + 32 + c]);
            uint2 r3 = __ldg(&feat[e3.x * 48 + 32 + c]);
            float w0 = __int_as_float(e0.y), w1 = __int_as_float(e1.y);
            float w2 = __int_as_float(e2.y), w3 = __int_as_float(e3.y);
            wsumA += w0 + w1 + w2 + w3;
            h4acc(r0, w0, accA);
            h4acc(r1, w1, accA);
            h4acc(r2, w2, accA);
            h4acc(r3, w3, accA);
        }
        for (; i < e; i++) {
            int2 ed = g_pedge[i];
            float w = __int_as_float(ed.y);
            uint2 r = __ldg(&feat[ed.x * 48 + 32 + c]);
            wsumA += w;
            h4acc(r, w, accA);
        }
    }

    int sc = c ^ (swap << 3);
    float4 accB = make_float4(0.f, 0.f, 0.f, 0.f);
    float wsumB = 0.f;
    {
        int b = g_noff[n], e = g_noff[n + 1];
        int i = b;
        for (; i + 4 <= e; i += 4) {
            int2 e0 = g_nedge[i + 0];
            int2 e1 = g_nedge[i + 1];
            int2 e2 = g_nedge[i + 2];
            int2 e3 = g_nedge[i + 3];
            uint2 r0 = __ldg(&feat[e0.x * 48 + 32 + sc]);
            uint2 r1 = __ldg(&feat[e1.x * 48 + 32 + sc]);
            uint2 r2 = __ldg(&feat[e2.x * 48 + 32 + sc]);
            uint2 r3 = __ldg(&feat[e3.x * 48 + 32 + sc]);
            float w0 = __int_as_float(e0.y), w1 = __int_as_float(e1.y);
            float w2 = __int_as_float(e2.y), w3 = __int_as_float(e3.y);
            wsumB += w0 + w1 + w2 + w3;
            h4acc(r0, w0, accB);
            h4acc(r1, w1, accB);
            h4acc(r2, w2, accB);
            h4acc(r3, w3, accB);
        }
        for (; i < e; i++) {
            int2 ed = g_nedge[i];
            float w = __int_as_float(ed.y);
            uint2 r = __ldg(&feat[ed.x * 48 + 32 + sc]);
            wsumB += w;
            h4acc(r, w, accB);
        }
    }

    float invA = 1.f / fmaxf(wsumA, 1e-12f);
    float invB = 1.f / fmaxf(wsumB, 1e-12f);
    __half2 a0 = __floats2half2_rn(accA.x * invA, accA.y * invA);
    __half2 a1 = __floats2half2_rn(accA.z * invA, accA.w * invA);
    __half2 b0 = __floats2half2_rn(accB.x * invB, accB.y * invB);
    __half2 b1 = __floats2half2_rn(accB.z * invB, accB.w * invB);
    uint2 ua, ub;
    ua.x = *reinterpret_cast<const unsigned*>(&a0);
    ua.y = *reinterpret_cast<const unsigned*>(&a1);
    ub.x = *reinterpret_cast<const unsigned*>(&b0);
    ub.y = *reinterpret_cast<const unsigned*>(&b1);
    reinterpret_cast<uint2*>(dstA)[n * 48 + c] = ua;
    reinterpret_cast<uint2*>(dstA)[n * 48 + 16 + c] = ub;
}

// ---------------- tensor-core GEMM + tanh epilogue ---------------------------
// C[NN,64] = tanh(A[NN,K] @ W[K,64] + bias). A,W fp16; accum fp32.
// A is staged through warp-private smem in 96-column phases so fragment loads
// use LDSM instead of scattered per-lane global U16 loads. The 4KB warp pad is
// reused (warp-synchronous) for the fp32 epilogue staging.
template <int K, bool FP32OUT>
__global__ __launch_bounds__(128) void gemm_kernel(
    const __half* __restrict__ A, const __half* __restrict__ W,
    const float* __restrict__ bias,
    __half* __restrict__ outh, float* __restrict__ outf, int out_stride) {
    __shared__ __align__(32) __half sW[K * 64];
    __shared__ float sB[64];
    __shared__ __align__(16) unsigned char spad[4][4096];

    int tid = threadIdx.x;
    for (int i = tid; i < K * 8; i += 128)
        reinterpret_cast<uint4*>(sW)[i] = reinterpret_cast<const uint4*>(W)[i];
    if (tid < 64) sB[tid] = bias[tid];
    __syncthreads();

    int warp = tid >> 5;
    int lane = tid & 31;
    int tile = blockIdx.x * 4 + warp;
    if (tile >= NTILES) return;

    wmma::fragment<wmma::accumulator, 16, 16, 16, float> c[4];
#pragma unroll
    for (int j = 0; j < 4; j++) wmma::fill_fragment(c[j], 0.f);

    const __half* Arow = A + (size_t)tile * 16 * K;
    __half* stage = reinterpret_cast<__half*>(spad[warp]);

    constexpr int NPH = (K + 95) / 96;        // 192 -> 2 phases, 64 -> 1
#pragma unroll
    for (int ph = 0; ph < NPH; ph++) {
        const int kbase = ph * 96;
        const int kw = (K - kbase < 96) ? (K - kbase) : 96;   // 96 or 64
        const int nu4 = kw / 8;               // uint4 per row (12 or 8)
        // copy 16 rows x kw halves into warp-private smem (vectorized)
        for (int i = lane; i < 16 * nu4; i += 32) {
            int r = i / nu4, cc = i % nu4;
            reinterpret_cast<uint4*>(stage + r * kw)[cc] =
                *reinterpret_cast<const uint4*>(Arow + r * K + kbase + cc * 8);
        }
        __syncwarp();
#pragma unroll
        for (int k0 = 0; k0 < 96 && k0 < kw; k0 += 16) {
            wmma::fragment<wmma::matrix_a, 16, 16, 16, __half, wmma::row_major> a;
            wmma::load_matrix_sync(a, stage + k0, kw);
#pragma unroll
            for (int j = 0; j < 4; j++) {
                wmma::fragment<wmma::matrix_b, 16, 16, 16, __half, wmma::row_major> b;
                wmma::load_matrix_sync(b, sW + (kbase + k0) * 64 + j * 16, 64);
                wmma::mma_sync(c[j], a, b, c[j]);
            }
        }
        __syncwarp();
    }

    float* cstage = reinterpret_cast<float*>(spad[warp]);
#pragma unroll
    for (int j = 0; j < 4; j++)
        wmma::store_matrix_sync(cstage + j * 16, c[j], 64, wmma::mem_row_major);
    __syncwarp();

    size_t rowbase = (size_t)tile * 16;
    if (FP32OUT) {
        for (int i = lane; i < 16 * 64; i += 32) {
            int r = i >> 6, col = i & 63;
            outf[(rowbase + r) * 64 + col] = tanha(cstage[i] + sB[col]);
        }
    } else {
        for (int i = lane; i < 16 * 32; i += 32) {
            int r = i >> 5, cp = i & 31;
            float v0 = tanha(cstage[r * 64 + 2 * cp] + sB[2 * cp]);
            float v1 = tanha(cstage[r * 64 + 2 * cp + 1] + sB[2 * cp + 1]);
            reinterpret_cast<__half2*>(outh + (rowbase + r) * out_stride)[cp] =
                __floats2half2_rn(v0, v1);
        }
    }
}

// ---------------- launch -----------------------------------------------------
extern "C" void kernel_launch(void* const* d_in, const int* in_sizes, int n_in,
                              void* d_out, int out_size) {
    const int*   pei  = (const int*)d_in[0];
    const int*   nei  = (const int*)d_in[1];
    const float* pw   = (const float*)d_in[2];
    const float* nw   = (const float*)d_in[3];
    const float* x    = (const float*)d_in[4];
    const float* w1p  = (const float*)d_in[5];
    const float* b1p  = (const float*)d_in[6];
    const float* w1n  = (const float*)d_in[7];
    const float* b1n  = (const float*)d_in[8];
    const float* w2p  = (const float*)d_in[9];
    const float* b2p  = (const float*)d_in[10];
    const float* w2n  = (const float*)d_in[11];
    const float* b2n  = (const float*)d_in[12];
    const float* wout = (const float*)d_in[13];
    const float* bout = (const float*)d_in[14];
    float* out = (float*)d_out;

    const int GB = (NN * 16 + 255) / 256;

    static __half *pA1 = nullptr, *pA2 = nullptr, *pz2 = nullptr;
    static __half *pW1 = nullptr, *pW2 = nullptr, *pWo = nullptr;
    static float *pb1 = nullptr, *pb2 = nullptr, *pb3 = nullptr;
    if (!pA1) {
        void* p;
        cudaGetSymbolAddress(&p, g_A1); pA1 = (__half*)p;
        cudaGetSymbolAddress(&p, g_A2); pA2 = (__half*)p;
        cudaGetSymbolAddress(&p, g_z2); pz2 = (__half*)p;
        cudaGetSymbolAddress(&p, g_W1); pW1 = (__half*)p;
        cudaGetSymbolAddress(&p, g_W2); pW2 = (__half*)p;
        cudaGetSymbolAddress(&p, g_Wo); pWo = (__half*)p;
        cudaGetSymbolAddress(&p, g_b1); pb1 = (float*)p;
        cudaGetSymbolAddress(&p, g_b2); pb2 = (float*)p;
        cudaGetSymbolAddress(&p, g_b3); pb3 = (float*)p;
    }

    // #0: prep + weight folding + hist
    prep_all_kernel<<<PB + WB + EB, 256>>>((const float4*)x,
                                           w1p, b1p, w1n, b1n,
                                           w2p, b2p, w2n, b2n, wout, bout,
                                           pei, nei);
    // #1: per-block scans
    scan1_kernel<<<dim3(NBLK, 2), 1024>>>();
    // #2: finalize offsets (+ re-zero counters) and fill CSR
    fill2_kernel<<<FINB + EB, 256>>>(pei, nei, pw, nw);

    // #3: gather 1 (profiled) — x-means into A1
    gather_kernel<<<GB, 256>>>(pA1, pA1, 0);
    // #4: GEMM layer 1 -> z into A2 cols 128:192
    gemm_kernel<192, false><<<GEMMG, 128>>>(pA1, pW1, pb1, pA2 + 128, nullptr, 192);
    // #5: gather 2 (neg swaps halves) — z-means into A2
    gather_kernel<<<GB, 256>>>(pA2, pA2, 1);
    // #6: GEMM layer 2 -> z2
    gemm_kernel<192, false><<<GEMMG, 128>>>(pA2, pW2, pb2, pz2, nullptr, 64);
    // #7: GEMM layer 3 -> out
    gemm_kernel<64, true><<<GEMMG, 128>>>(pz2, pWo, pb3, nullptr, out, 64);

    (void)in_sizes; (void)n_in; (void)out_size;
}